// round 2
// baseline (speedup 1.0000x reference)
#include <cuda_runtime.h>
#include <cuda_bf16.h>
#include <cstddef>

// ---------------- Problem constants ----------------
#define B_    32
#define H_    32
#define KV_   8
#define G_    4        // H_/KV_
#define S_    4096
#define D_    64
#define HID_  2048
#define FF_   8192
#define V_    32000

// ---------------- Device scratch (no allocs allowed) ----------------
__device__ float g_ctx[B_ * HID_];        // attention context, [b][h*64+d]
__device__ float g_h  [B_ * HID_];        // attn_out + residual (res2)
__device__ float g_hn [B_ * HID_];        // LN2 output
__device__ float g_ff [B_ * FF_];         // gelu(W1 x + b1)
__device__ float g_t  [B_ * HID_];        // mlp_out + res2
__device__ float g_hf [B_ * HID_];        // final LN output
__device__ float g_part[2097152];         // split-K partials (max 32*32*2048)

// ---------------- helpers ----------------
__device__ __forceinline__ unsigned long long dup2(float f) {
    unsigned long long r;
    asm("mov.b64 %0, {%1, %1};" : "=l"(r) : "f"(f));
    return r;
}
__device__ __forceinline__ void fma2(unsigned long long &acc, unsigned long long w,
                                     unsigned long long x) {
    asm("fma.rn.f32x2 %0, %1, %2, %0;" : "+l"(acc) : "l"(w), "l"(x));
}
__device__ __forceinline__ float lo32(unsigned long long u) {
    return __int_as_float((int)(unsigned)(u & 0xffffffffull));
}
__device__ __forceinline__ float hi32(unsigned long long u) {
    return __int_as_float((int)(unsigned)(u >> 32));
}

// generic block reduce (sum: op=0, max: op=1); red must hold >= nwarps floats
__device__ __forceinline__ float block_reduce(float v, float* red, int op) {
    int t = threadIdx.x, lane = t & 31, w = t >> 5;
    int nw = blockDim.x >> 5;
    #pragma unroll
    for (int o = 16; o > 0; o >>= 1) {
        float o2 = __shfl_down_sync(0xffffffffu, v, o);
        v = op ? fmaxf(v, o2) : v + o2;
    }
    if (lane == 0) red[w] = v;
    __syncthreads();
    if (w == 0) {
        v = (lane < nw) ? red[lane] : (op ? -3.0e38f : 0.0f);
        #pragma unroll
        for (int o = 8; o > 0; o >>= 1) {
            float o2 = __shfl_down_sync(0xffffffffu, v, o);
            v = op ? fmaxf(v, o2) : v + o2;
        }
        if (lane == 0) red[0] = v;
    }
    __syncthreads();
    float r = red[0];
    __syncthreads();
    return r;
}

// ======================= Attention =======================
// grid: B_*KV_ = 256 blocks; block: 512 threads. Each block handles all G_=4
// heads of one (b,kv) pair so ks/vs stream from HBM exactly once.
// smem: scores 64KB + q 1KB + pacc 32KB + scratch ~= 98.4KB -> 2 CTAs/SM.
__global__ __launch_bounds__(512)
void attn_kernel(const float* __restrict__ q,
                 const float* __restrict__ ks,
                 const float* __restrict__ vs) {
    extern __shared__ float sm[];
    float* sc   = sm;                       // [4][4096] scores -> probs
    float* sq   = sc + 4 * S_;              // [4][64] q vectors
    float* pacc = sq + 256;                 // [32][4][64] partial ctx
    float* red  = pacc + 32 * 256;          // [16] reduce scratch
    float* invs = red + 16;                 // [4]

    int t  = threadIdx.x;
    int bx = blockIdx.x;
    int b  = bx >> 3, kv = bx & 7;
    const float* kbase = ks + ((size_t)(b * KV_ + kv)) * S_ * D_;
    const float* vbase = vs + ((size_t)(b * KV_ + kv)) * S_ * D_;

    if (t < 256) {
        int hh = t >> 6, d = t & 63;
        sq[hh * 64 + d] = q[((size_t)b * H_ + (kv * G_ + hh)) * D_ + d];
    }
    __syncthreads();

    // ---- Phase 1: scores. 8-lane groups: lane group grp = lane>>3 picks s,
    // sub = lane&7 covers d in [sub*8, sub*8+8). Coalesced 1KB per warp iter.
    {
        int w = t >> 5, lane = t & 31;
        int grp = lane >> 3, sub = lane & 7;
        float4 qv[4][2];
        #pragma unroll
        for (int hh = 0; hh < 4; hh++) {
            qv[hh][0] = *(const float4*)&sq[hh * 64 + sub * 8];
            qv[hh][1] = *(const float4*)&sq[hh * 64 + sub * 8 + 4];
        }
        const float scale = 0.125f;   // 1/sqrt(64)
        for (int i = 0; i < 64; i++) {
            int s = i * 64 + w * 4 + grp;
            const float4* kr = (const float4*)(kbase + (size_t)s * D_ + sub * 8);
            float4 k0 = kr[0], k1 = kr[1];
            float p[4];
            #pragma unroll
            for (int hh = 0; hh < 4; hh++) {
                p[hh] = k0.x * qv[hh][0].x + k0.y * qv[hh][0].y
                      + k0.z * qv[hh][0].z + k0.w * qv[hh][0].w
                      + k1.x * qv[hh][1].x + k1.y * qv[hh][1].y
                      + k1.z * qv[hh][1].z + k1.w * qv[hh][1].w;
                p[hh] += __shfl_down_sync(0xffffffffu, p[hh], 4, 8);
                p[hh] += __shfl_down_sync(0xffffffffu, p[hh], 2, 8);
                p[hh] += __shfl_down_sync(0xffffffffu, p[hh], 1, 8);
            }
            if (sub == 0) {
                sc[0 * S_ + s] = p[0] * scale;
                sc[1 * S_ + s] = p[1] * scale;
                sc[2 * S_ + s] = p[2] * scale;
                sc[3 * S_ + s] = p[3] * scale;
            }
        }
    }
    __syncthreads();

    // ---- Phase 2: softmax (two-pass, per head)
    float lm[4] = {-3.0e38f, -3.0e38f, -3.0e38f, -3.0e38f};
    for (int j = t; j < S_; j += 512) {
        #pragma unroll
        for (int hh = 0; hh < 4; hh++) lm[hh] = fmaxf(lm[hh], sc[hh * S_ + j]);
    }
    float mv[4];
    #pragma unroll
    for (int hh = 0; hh < 4; hh++) mv[hh] = block_reduce(lm[hh], red, 1);

    float ls[4] = {0.f, 0.f, 0.f, 0.f};
    for (int j = t; j < S_; j += 512) {
        #pragma unroll
        for (int hh = 0; hh < 4; hh++) {
            float e = expf(sc[hh * S_ + j] - mv[hh]);
            sc[hh * S_ + j] = e;
            ls[hh] += e;
        }
    }
    #pragma unroll
    for (int hh = 0; hh < 4; hh++) {
        float sv = block_reduce(ls[hh], red, 0);
        if (t == 0) invs[hh] = 1.0f / sv;
    }
    __syncthreads();

    // ---- Phase 3: ctx = P @ V, float4 along d.
    // thread = (sg, dq): 32 s-groups x 16 d-quads. 128 iters of LDG.128.
    {
        int dq = t & 15, sg = t >> 4;
        float4 a0 = {0,0,0,0}, a1 = {0,0,0,0}, a2 = {0,0,0,0}, a3 = {0,0,0,0};
        #pragma unroll 4
        for (int s = sg; s < S_; s += 32) {
            float4 vv = *(const float4*)(vbase + (size_t)s * D_ + dq * 4);
            float p0 = sc[0 * S_ + s], p1 = sc[1 * S_ + s];
            float p2 = sc[2 * S_ + s], p3 = sc[3 * S_ + s];
            a0.x += p0 * vv.x; a0.y += p0 * vv.y; a0.z += p0 * vv.z; a0.w += p0 * vv.w;
            a1.x += p1 * vv.x; a1.y += p1 * vv.y; a1.z += p1 * vv.z; a1.w += p1 * vv.w;
            a2.x += p2 * vv.x; a2.y += p2 * vv.y; a2.z += p2 * vv.z; a2.w += p2 * vv.w;
            a3.x += p3 * vv.x; a3.y += p3 * vv.y; a3.z += p3 * vv.z; a3.w += p3 * vv.w;
        }
        *(float4*)&pacc[sg * 256 + 0 * 64 + dq * 4] = a0;
        *(float4*)&pacc[sg * 256 + 1 * 64 + dq * 4] = a1;
        *(float4*)&pacc[sg * 256 + 2 * 64 + dq * 4] = a2;
        *(float4*)&pacc[sg * 256 + 3 * 64 + dq * 4] = a3;
    }
    __syncthreads();
    if (t < 256) {
        int hh = t >> 6, d = t & 63;
        float v = 0.f;
        #pragma unroll
        for (int sg = 0; sg < 32; sg++) v += pacc[sg * 256 + hh * 64 + d];
        g_ctx[(size_t)b * HID_ + (kv * G_ + hh) * 64 + d] = v * invs[hh];
    }
}

// ======================= Skinny GEMM (M=32) =======================
// part[kb][b][n] = sum over k in [kb*kchunk, (kb+1)*kchunk) of x[b][k]*W[n][k]
// BN=256 n per block, BK=32 k per tile, thread tile 8b x 4n via fma.rn.f32x2.
#define BN_ 256
#define BK_ 32

__global__ __launch_bounds__(256, 2)
void gemm_part(const float* __restrict__ x, const float* __restrict__ W,
               float* __restrict__ part, int K, int N, int kchunk) {
    __shared__ __align__(16) float wts[BK_][BN_ + 4];   // [k][n], 260 stride
    __shared__ __align__(16) float xs [BK_][36];        // [k][b], 36 stride

    int t  = threadIdx.x;
    int nb = blockIdx.x, kb = blockIdx.y;
    int k0 = kb * kchunk;
    int ntiles = kchunk / BK_;

    int tn = t & 63;           // 0..63 -> 4 n each
    int tb = t >> 6;           // 0..3  -> 8 b each
    int bbase = tb * 8;
    int nbase = nb * BN_ + tn * 4;

    unsigned long long acc[8][2];
    #pragma unroll
    for (int bi = 0; bi < 8; bi++) { acc[bi][0] = 0ull; acc[bi][1] = 0ull; }

    float4 wpf[8];
    float4 xpf;

    // prologue: load tile 0
    {
        #pragma unroll
        for (int p = 0; p < 8; p++) {
            int i = p * 256 + t;
            int kq = i & 7, nl = i >> 3;
            wpf[p] = *(const float4*)&W[((size_t)(nb * BN_ + nl)) * K + k0 + kq * 4];
        }
        int kq = t & 7, bb = t >> 3;
        xpf = *(const float4*)&x[(size_t)bb * K + k0 + kq * 4];
        #pragma unroll
        for (int p = 0; p < 8; p++) {
            int i = p * 256 + t;
            int kq2 = i & 7, nl = i >> 3;
            wts[kq2 * 4 + 0][nl] = wpf[p].x;
            wts[kq2 * 4 + 1][nl] = wpf[p].y;
            wts[kq2 * 4 + 2][nl] = wpf[p].z;
            wts[kq2 * 4 + 3][nl] = wpf[p].w;
        }
        xs[kq * 4 + 0][bb] = xpf.x;
        xs[kq * 4 + 1][bb] = xpf.y;
        xs[kq * 4 + 2][bb] = xpf.z;
        xs[kq * 4 + 3][bb] = xpf.w;
    }
    __syncthreads();

    for (int kt = 0; kt < ntiles; kt++) {
        // prefetch next tile into registers while computing
        if (kt + 1 < ntiles) {
            size_t kc = (size_t)k0 + (size_t)(kt + 1) * BK_;
            #pragma unroll
            for (int p = 0; p < 8; p++) {
                int i = p * 256 + t;
                int kq = i & 7, nl = i >> 3;
                wpf[p] = *(const float4*)&W[((size_t)(nb * BN_ + nl)) * K + kc + kq * 4];
            }
            int kq = t & 7, bb = t >> 3;
            xpf = *(const float4*)&x[(size_t)bb * K + kc + kq * 4];
        }

        #pragma unroll 4
        for (int kk = 0; kk < BK_; kk++) {
            ulonglong2 wp = *(const ulonglong2*)&wts[kk][tn * 4];
            float4 xa = *(const float4*)&xs[kk][bbase];
            float4 xb = *(const float4*)&xs[kk][bbase + 4];
            unsigned long long xd;
            xd = dup2(xa.x); fma2(acc[0][0], wp.x, xd); fma2(acc[0][1], wp.y, xd);
            xd = dup2(xa.y); fma2(acc[1][0], wp.x, xd); fma2(acc[1][1], wp.y, xd);
            xd = dup2(xa.z); fma2(acc[2][0], wp.x, xd); fma2(acc[2][1], wp.y, xd);
            xd = dup2(xa.w); fma2(acc[3][0], wp.x, xd); fma2(acc[3][1], wp.y, xd);
            xd = dup2(xb.x); fma2(acc[4][0], wp.x, xd); fma2(acc[4][1], wp.y, xd);
            xd = dup2(xb.y); fma2(acc[5][0], wp.x, xd); fma2(acc[5][1], wp.y, xd);
            xd = dup2(xb.z); fma2(acc[6][0], wp.x, xd); fma2(acc[6][1], wp.y, xd);
            xd = dup2(xb.w); fma2(acc[7][0], wp.x, xd); fma2(acc[7][1], wp.y, xd);
        }
        __syncthreads();

        if (kt + 1 < ntiles) {
            #pragma unroll
            for (int p = 0; p < 8; p++) {
                int i = p * 256 + t;
                int kq = i & 7, nl = i >> 3;
                wts[kq * 4 + 0][nl] = wpf[p].x;
                wts[kq * 4 + 1][nl] = wpf[p].y;
                wts[kq * 4 + 2][nl] = wpf[p].z;
                wts[kq * 4 + 3][nl] = wpf[p].w;
            }
            int kq = t & 7, bb = t >> 3;
            xs[kq * 4 + 0][bb] = xpf.x;
            xs[kq * 4 + 1][bb] = xpf.y;
            xs[kq * 4 + 2][bb] = xpf.z;
            xs[kq * 4 + 3][bb] = xpf.w;
            __syncthreads();
        }
    }

    #pragma unroll
    for (int bi = 0; bi < 8; bi++) {
        float4 o;
        o.x = lo32(acc[bi][0]); o.y = hi32(acc[bi][0]);
        o.z = lo32(acc[bi][1]); o.w = hi32(acc[bi][1]);
        *(float4*)&part[((size_t)(kb * B_ + bbase + bi)) * N + nbase] = o;
    }
}

// ======================= Epilogue (split-K reduce + bias/res/gelu) =====
// float4-vectorized: one thread handles 4 consecutive n of one row b.
__global__ __launch_bounds__(256)
void epilogue(const float* __restrict__ part, int ksplit, int N,
              const float* __restrict__ bias, const float* __restrict__ res,
              int dogelu, float* __restrict__ out) {
    int q = blockIdx.x * 256 + threadIdx.x;      // quad index
    int nq = N >> 2;
    int total = B_ * nq;
    if (q >= total) return;
    int b = q / nq, n4 = (q - b * nq) << 2;
    float4 s = {0.f, 0.f, 0.f, 0.f};
    for (int kb = 0; kb < ksplit; kb++) {
        float4 p = *(const float4*)&part[((size_t)(kb * B_ + b)) * N + n4];
        s.x += p.x; s.y += p.y; s.z += p.z; s.w += p.w;
    }
    if (bias) {
        float4 bv = *(const float4*)&bias[n4];
        s.x += bv.x; s.y += bv.y; s.z += bv.z; s.w += bv.w;
    }
    if (res) {
        float4 rv = *(const float4*)&res[(size_t)b * N + n4];
        s.x += rv.x; s.y += rv.y; s.z += rv.z; s.w += rv.w;
    }
    if (dogelu) {
        s.x = 0.5f * s.x * (1.0f + erff(s.x * 0.70710678118654752f));
        s.y = 0.5f * s.y * (1.0f + erff(s.y * 0.70710678118654752f));
        s.z = 0.5f * s.z * (1.0f + erff(s.z * 0.70710678118654752f));
        s.w = 0.5f * s.w * (1.0f + erff(s.w * 0.70710678118654752f));
    }
    *(float4*)&out[(size_t)b * N + n4] = s;
}

// ======================= LayerNorm =======================
__global__ __launch_bounds__(256)
void ln_kernel(const float* __restrict__ in, const float* __restrict__ g,
               const float* __restrict__ bt, float* __restrict__ out) {
    __shared__ float red[32];
    int b = blockIdx.x, t = threadIdx.x;
    const float* row = in + (size_t)b * HID_;
    float v[8];
    #pragma unroll
    for (int i = 0; i < 8; i++) v[i] = row[t + i * 256];
    float s = 0.f;
    #pragma unroll
    for (int i = 0; i < 8; i++) s += v[i];
    float mean = block_reduce(s, red, 0) * (1.0f / HID_);
    float s2 = 0.f;
    #pragma unroll
    for (int i = 0; i < 8; i++) { float d = v[i] - mean; s2 += d * d; }
    float var = block_reduce(s2, red, 0) * (1.0f / HID_);
    float inv = rsqrtf(var + 1e-5f);
    #pragma unroll
    for (int i = 0; i < 8; i++) {
        int n = t + i * 256;
        out[(size_t)b * HID_ + n] = (v[i] - mean) * inv * g[n] + bt[n];
    }
}

// ======================= Launch =======================
extern "C" void kernel_launch(void* const* d_in, const int* in_sizes, int n_in,
                              void* d_out, int out_size) {
    const float* residual = (const float*)d_in[0];
    const float* q        = (const float*)d_in[1];
    const float* ks       = (const float*)d_in[2];
    const float* vs       = (const float*)d_in[3];
    const float* Wo       = (const float*)d_in[4];
    const float* bo       = (const float*)d_in[5];
    const float* g2       = (const float*)d_in[6];
    const float* b2       = (const float*)d_in[7];
    const float* W1       = (const float*)d_in[8];
    const float* b1       = (const float*)d_in[9];
    const float* W2       = (const float*)d_in[10];
    const float* b2m      = (const float*)d_in[11];
    const float* gf       = (const float*)d_in[12];
    const float* bf       = (const float*)d_in[13];
    const float* Wlm      = (const float*)d_in[14];
    float* out = (float*)d_out;

    float *ctx, *h, *hn, *ff, *tt, *hf, *part;
    cudaGetSymbolAddress((void**)&ctx,  g_ctx);
    cudaGetSymbolAddress((void**)&h,    g_h);
    cudaGetSymbolAddress((void**)&hn,   g_hn);
    cudaGetSymbolAddress((void**)&ff,   g_ff);
    cudaGetSymbolAddress((void**)&tt,   g_t);
    cudaGetSymbolAddress((void**)&hf,   g_hf);
    cudaGetSymbolAddress((void**)&part, g_part);

    // --- attention ---
    int smem = (4 * S_ + 256 + 32 * 256 + 16 + 4) * (int)sizeof(float); // ~98.4 KB
    cudaFuncSetAttribute(attn_kernel, cudaFuncAttributeMaxDynamicSharedMemorySize, smem);
    attn_kernel<<<B_ * KV_, 512, smem>>>(q, ks, vs);

    // --- h = ctx @ Wo^T + bo + residual ---
    {
        dim3 grd(HID_ / BN_, 32);                    // (8, 32), kchunk 64
        gemm_part<<<grd, 256>>>(ctx, Wo, part, HID_, HID_, HID_ / 32);
        epilogue<<<(B_ * HID_ / 4 + 255) / 256, 256>>>(part, 32, HID_, bo, residual, 0, h);
    }
    // --- LN2 ---
    ln_kernel<<<B_, 256>>>(h, g2, b2, hn);
    // --- ff = gelu(hn @ W1^T + b1) ---
    {
        dim3 grd(FF_ / BN_, 8);                      // (32, 8), kchunk 256
        gemm_part<<<grd, 256>>>(hn, W1, part, HID_, FF_, HID_ / 8);
        epilogue<<<(B_ * FF_ / 4 + 255) / 256, 256>>>(part, 8, FF_, b1, nullptr, 1, ff);
    }
    // --- t = ff @ W2^T + b2m + h ---
    {
        dim3 grd(HID_ / BN_, 32);                    // (8, 32), kchunk 256
        gemm_part<<<grd, 256>>>(ff, W2, part, FF_, HID_, FF_ / 32);
        epilogue<<<(B_ * HID_ / 4 + 255) / 256, 256>>>(part, 32, HID_, b2m, h, 0, tt);
    }
    // --- LNf ---
    ln_kernel<<<B_, 256>>>(tt, gf, bf, hf);
    // --- logits = hf @ Wlm^T ---
    {
        dim3 grd(V_ / BN_, 2);                       // (125, 2), kchunk 1024
        gemm_part<<<grd, 256>>>(hf, Wlm, part, HID_, V_, HID_ / 2);
        epilogue<<<(B_ * V_ / 4 + 255) / 256, 256>>>(part, 2, V_, nullptr, nullptr, 0, out);
    }
}